// round 9
// baseline (speedup 1.0000x reference)
#include <cuda_runtime.h>
#include <cuda_bf16.h>
#include <stdint.h>

#define BATCH 8
#define SEQ   2048
#define EDIM  1024
#define HDIM  64
#define MTOT  (BATCH*SEQ)

// scratch (device globals: no allocation allowed)
__device__ __nv_bfloat16  g_qh [MTOT*HDIM], g_ql [MTOT*HDIM];
__device__ __nv_bfloat16  g_kh [MTOT*HDIM], g_kl [MTOT*HDIM];
__device__ uint32_t       g_vph[(MTOT/2)*HDIM], g_vpl[(MTOT/2)*HDIM];
__device__ uint32_t       g_wph[512*192],       g_wpl[512*192];
__device__ float          g_po[2][MTOT*HDIM];   // split-K partial O
__device__ float          g_pm[2][MTOT];        // partial row max (log2 domain)
__device__ float          g_pl[2][MTOT];        // partial row sum

// ---------------------------------------------------------------------------
// helpers
// ---------------------------------------------------------------------------
__device__ __forceinline__ void mma_bf16(float& d0, float& d1, float& d2, float& d3,
                                         uint32_t a0, uint32_t a1, uint32_t a2, uint32_t a3,
                                         uint32_t b0, uint32_t b1)
{
    asm("mma.sync.aligned.m16n8k16.row.col.f32.bf16.bf16.f32 "
        "{%0,%1,%2,%3},{%4,%5,%6,%7},{%8,%9},{%0,%1,%2,%3};"
        : "+f"(d0), "+f"(d1), "+f"(d2), "+f"(d3)
        : "r"(a0), "r"(a1), "r"(a2), "r"(a3), "r"(b0), "r"(b1));
}

__device__ __forceinline__ void split2(float x, __nv_bfloat16& h, __nv_bfloat16& l)
{
    h = __float2bfloat16(x);
    l = __float2bfloat16(x - __bfloat162float(h));
}

__device__ __forceinline__ void split_pack(float x0, float x1, uint32_t& hp, uint32_t& lp)
{
    __nv_bfloat16 h0, l0, h1, l1;
    split2(x0, h0, l0);
    split2(x1, h1, l1);
    __nv_bfloat162 hh = __halves2bfloat162(h0, h1);
    __nv_bfloat162 ll = __halves2bfloat162(l0, l1);
    hp = *reinterpret_cast<uint32_t*>(&hh);
    lp = *reinterpret_cast<uint32_t*>(&ll);
}

__device__ __forceinline__ float ex2f(float x)
{
    float y;
    asm("ex2.approx.f32 %0, %1;" : "=f"(y) : "f"(x));
    return y;
}

__device__ __forceinline__ void cp16(uint32_t dst, const void* src)
{
    asm volatile("cp.async.cg.shared.global [%0], [%1], 16;" :: "r"(dst), "l"(src));
}
__device__ __forceinline__ uint32_t smem_u32(const void* p)
{
    uint32_t a;
    asm("{ .reg .u64 t; cvta.to.shared.u64 t, %1; cvt.u32.u64 %0, t; }" : "=r"(a) : "l"(p));
    return a;
}
#define CP_COMMIT() asm volatile("cp.async.commit_group;" ::: "memory")

// ---------------------------------------------------------------------------
// prep kernel: pack W (k-pair hi/lo u32)
// ---------------------------------------------------------------------------
__global__ void prep_w(const float* __restrict__ wk, const float* __restrict__ wq,
                       const float* __restrict__ wv)
{
    int idx = blockIdx.x * 256 + threadIdx.x;       // 512*192 = 98304
    int kp = idx / 192, c = idx - kp * 192;
    const float* wp = (c < 64) ? wk : ((c < 128) ? wq : wv);
    int cc = c & 63;
    float w0 = wp[(2 * kp)     * HDIM + cc];
    float w1 = wp[(2 * kp + 1) * HDIM + cc];
    uint32_t hp, lp;
    split_pack(w0, w1, hp, lp);
    g_wph[idx] = hp;
    g_wpl[idx] = lp;
}

// ---------------------------------------------------------------------------
// Kernel 1: fused QKV projection, HMMA bf16 split, double-buffered.
// Epilogue: K hi/lo, Q pre-scaled hi/lo, V packed (prep_v fused via shfl).
// (Proven round-7 version, unchanged.)
// ---------------------------------------------------------------------------
#define AP   40
#define BP   200
#define XH_OFF 0
#define XL_OFF 20480
#define WH_OFF 40960
#define WL_OFF 66560
#define PROJ_SMEM 92160

__global__ void __launch_bounds__(256) proj_kernel(const float* __restrict__ x)
{
    extern __shared__ unsigned char sm[];
    const uint32_t smb = smem_u32(sm);

    const int tid   = threadIdx.x;
    const int lane  = tid & 31;
    const int warp  = tid >> 5;
    const int warpM = warp >> 2;
    const int warpN = warp & 3;
    const int g     = lane >> 2;
    const int tg    = lane & 3;
    const int row0  = blockIdx.x * 128;

    float acc[4][6][4];
#pragma unroll
    for (int i = 0; i < 4; i++)
#pragma unroll
        for (int j = 0; j < 6; j++)
#pragma unroll
            for (int r = 0; r < 4; r++) acc[i][j][r] = 0.f;

    float4 xr[4];
    int xrr[4], xcc[4];
#pragma unroll
    for (int l = 0; l < 4; l++) {
        int idx = tid + l * 256;
        xrr[l] = idx >> 3;
        xcc[l] = (idx & 7) << 2;
    }

#pragma unroll
    for (int l = 0; l < 4; l++)
        xr[l] = *(const float4*)&x[(size_t)(row0 + xrr[l]) * EDIM + xcc[l]];
    {
        __nv_bfloat16* XH = (__nv_bfloat16*)(sm + XH_OFF);
        __nv_bfloat16* XL = (__nv_bfloat16*)(sm + XL_OFF);
#pragma unroll
        for (int l = 0; l < 4; l++) {
            __nv_bfloat16 h0,l0,h1,l1,h2,l2,h3,l3;
            split2(xr[l].x, h0, l0); split2(xr[l].y, h1, l1);
            split2(xr[l].z, h2, l2); split2(xr[l].w, h3, l3);
            int base = xrr[l] * AP + xcc[l];
            *(__nv_bfloat162*)&XH[base]     = __halves2bfloat162(h0, h1);
            *(__nv_bfloat162*)&XH[base + 2] = __halves2bfloat162(h2, h3);
            *(__nv_bfloat162*)&XL[base]     = __halves2bfloat162(l0, l1);
            *(__nv_bfloat162*)&XL[base + 2] = __halves2bfloat162(l2, l3);
        }
    }
#pragma unroll
    for (int i = 0; i < 3; i++) {
        int idx = tid + i * 256;
        int r   = idx / 48;
        int cc  = idx - r * 48;
        cp16(smb + WH_OFF + r * (BP*4) + cc * 16, (const char*)(g_wph + (size_t)r * 192) + cc * 16);
        cp16(smb + WL_OFF + r * (BP*4) + cc * 16, (const char*)(g_wpl + (size_t)r * 192) + cc * 16);
    }
    CP_COMMIT();

#pragma unroll 1
    for (int k = 0; k < 32; k++) {
        const int buf = k & 1;
        if (k < 31) {
            const int k0n = (k + 1) * 32;
#pragma unroll
            for (int l = 0; l < 4; l++)
                xr[l] = *(const float4*)&x[(size_t)(row0 + xrr[l]) * EDIM + k0n + xcc[l]];
            const int kp0 = k0n >> 1;
            const uint32_t wdst = smb + ((k + 1) & 1) * 12800;
#pragma unroll
            for (int i = 0; i < 3; i++) {
                int idx = tid + i * 256;
                int r   = idx / 48;
                int cc  = idx - r * 48;
                cp16(wdst + WH_OFF + r * (BP*4) + cc * 16, (const char*)(g_wph + (size_t)(kp0 + r) * 192) + cc * 16);
                cp16(wdst + WL_OFF + r * (BP*4) + cc * 16, (const char*)(g_wpl + (size_t)(kp0 + r) * 192) + cc * 16);
            }
            CP_COMMIT();
            asm volatile("cp.async.wait_group 1;" ::: "memory");
        } else {
            asm volatile("cp.async.wait_group 0;" ::: "memory");
        }
        __syncthreads();

        const uint32_t* Ah32 = (const uint32_t*)(sm + XH_OFF + buf * 10240);
        const uint32_t* Al32 = (const uint32_t*)(sm + XL_OFF + buf * 10240);
        const uint32_t* Bh   = (const uint32_t*)(sm + WH_OFF + buf * 12800);
        const uint32_t* Bl   = (const uint32_t*)(sm + WL_OFF + buf * 12800);
        const int ap32 = AP / 2;

#pragma unroll
        for (int k16 = 0; k16 < 2; k16++) {
            uint32_t ah[4][4], al[4][4];
#pragma unroll
            for (int mt = 0; mt < 4; mt++) {
                int rb = (warpM * 64 + mt * 16 + g) * ap32 + k16 * 8 + tg;
                ah[mt][0] = Ah32[rb];
                ah[mt][1] = Ah32[rb + 8 * ap32];
                ah[mt][2] = Ah32[rb + 4];
                ah[mt][3] = Ah32[rb + 8 * ap32 + 4];
                al[mt][0] = Al32[rb];
                al[mt][1] = Al32[rb + 8 * ap32];
                al[mt][2] = Al32[rb + 4];
                al[mt][3] = Al32[rb + 8 * ap32 + 4];
            }
#pragma unroll
            for (int nt = 0; nt < 6; nt++) {
                int n  = warpN * 48 + nt * 8 + g;
                int kp = k16 * 8 + tg;
                uint32_t bh0 = Bh[kp * BP + n], bh1 = Bh[(kp + 4) * BP + n];
                uint32_t bl0 = Bl[kp * BP + n], bl1 = Bl[(kp + 4) * BP + n];
#pragma unroll
                for (int mt = 0; mt < 4; mt++) {
                    float* c = acc[mt][nt];
                    mma_bf16(c[0], c[1], c[2], c[3], ah[mt][0], ah[mt][1], ah[mt][2], ah[mt][3], bh0, bh1);
                    mma_bf16(c[0], c[1], c[2], c[3], al[mt][0], al[mt][1], al[mt][2], al[mt][3], bh0, bh1);
                    mma_bf16(c[0], c[1], c[2], c[3], ah[mt][0], ah[mt][1], ah[mt][2], ah[mt][3], bl0, bl1);
                }
            }
        }

        if (k < 31) {
            __nv_bfloat16* XH = (__nv_bfloat16*)(sm + XH_OFF + ((k + 1) & 1) * 10240);
            __nv_bfloat16* XL = (__nv_bfloat16*)(sm + XL_OFF + ((k + 1) & 1) * 10240);
#pragma unroll
            for (int l = 0; l < 4; l++) {
                __nv_bfloat16 h0,l0,h1,l1,h2,l2,h3,l3;
                split2(xr[l].x, h0, l0); split2(xr[l].y, h1, l1);
                split2(xr[l].z, h2, l2); split2(xr[l].w, h3, l3);
                int base = xrr[l] * AP + xcc[l];
                *(__nv_bfloat162*)&XH[base]     = __halves2bfloat162(h0, h1);
                *(__nv_bfloat162*)&XH[base + 2] = __halves2bfloat162(h2, h3);
                *(__nv_bfloat162*)&XL[base]     = __halves2bfloat162(l0, l1);
                *(__nv_bfloat162*)&XL[base + 2] = __halves2bfloat162(l2, l3);
            }
        }
        __syncthreads();
    }

    // ---- epilogue: K hi/lo, Q scaled hi/lo, V packed via shfl row-pairing ----
    const float CQ = 0.125f * 1.44269504088896340736f;   // 1/sqrt(H) * log2(e)
    uint32_t* qh32 = (uint32_t*)g_qh; uint32_t* ql32 = (uint32_t*)g_ql;
    uint32_t* kh32 = (uint32_t*)g_kh; uint32_t* kl32 = (uint32_t*)g_kl;
#pragma unroll
    for (int mt = 0; mt < 4; mt++) {
#pragma unroll
        for (int nt = 0; nt < 6; nt++) {
            int gcol = warpN * 48 + nt * 8 + 2 * tg;
            int seg  = gcol >> 6;
            int cc   = gcol & 63;
            int r0   = row0 + warpM * 64 + mt * 16 + g;
            float* c = acc[mt][nt];
            if (seg == 2) {
                float p0 = __shfl_xor_sync(0xffffffffu, c[0], 4);
                float p1 = __shfl_xor_sync(0xffffffffu, c[1], 4);
                float p2 = __shfl_xor_sync(0xffffffffu, c[2], 4);
                float p3 = __shfl_xor_sync(0xffffffffu, c[3], 4);
                if ((g & 1) == 0) {
                    uint32_t h0, l0, h1, l1;
                    split_pack(c[0], p0, h0, l0);
                    split_pack(c[1], p1, h1, l1);
                    int kp = r0 >> 1;
                    *(uint2*)&g_vph[kp * 64 + cc] = make_uint2(h0, h1);
                    *(uint2*)&g_vpl[kp * 64 + cc] = make_uint2(l0, l1);
                    split_pack(c[2], p2, h0, l0);
                    split_pack(c[3], p3, h1, l1);
                    int kp2 = (r0 + 8) >> 1;
                    *(uint2*)&g_vph[kp2 * 64 + cc] = make_uint2(h0, h1);
                    *(uint2*)&g_vpl[kp2 * 64 + cc] = make_uint2(l0, l1);
                }
            } else {
                uint32_t* dh = seg ? qh32 : kh32;
                uint32_t* dl = seg ? ql32 : kl32;
                float s0 = c[0], s1 = c[1], s2 = c[2], s3 = c[3];
                if (seg) { s0 *= CQ; s1 *= CQ; s2 *= CQ; s3 *= CQ; }
                uint32_t hp, lp;
                split_pack(s0, s1, hp, lp);
                dh[r0 * 32 + cc / 2] = hp;
                dl[r0 * 32 + cc / 2] = lp;
                split_pack(s2, s3, hp, lp);
                dh[(r0 + 8) * 32 + cc / 2] = hp;
                dl[(r0 + 8) * 32 + cc / 2] = lp;
            }
        }
    }
}

// ---------------------------------------------------------------------------
// Kernel 2: causal flash attention, block-level split-K partials.
// Block = 128 thr (4 warps), one q-tile, key-tile range [kb, ke).
// One stage = K+V; double-buffered with DISTANCE-1 prefetch issued at the
// top of each iteration (the proven round-3 pipeline shape). No mid-tile
// V wait; 2 barriers per tile.
// ---------------------------------------------------------------------------
#define KP32   36                       // K smem pitch (u32), rows 144B
#define VPP    68                       // V smem pitch (u32), rows 272B
#define STG    35840                    // KH 9216 + KL 9216 + VH 8704 + VL 8704
#define VH_O   18432
#define VL_O   27136
#define ATTN_SMEM (2*STG)               // 71680; 3 blocks/SM = 215040 <= 228K

__device__ __forceinline__ void fill_kv(uint32_t sb, int t, int kt,
                                        const __nv_bfloat16* kh, const __nv_bfloat16* kl,
                                        const uint32_t* vph, const uint32_t* vpl)
{
    const int k0  = kt * 64;
    const int kp0 = k0 >> 1;
#pragma unroll
    for (int i = 0; i < 4; i++) {
        int idx = t + i * 128;          // 0..511
        int r   = idx >> 3;
        int cc  = (idx & 7) * 16;
        cp16(sb + r * 144 + cc,        (const char*)(kh + (size_t)(k0 + r) * HDIM) + cc);
        cp16(sb + 9216 + r * 144 + cc, (const char*)(kl + (size_t)(k0 + r) * HDIM) + cc);
    }
#pragma unroll
    for (int i = 0; i < 4; i++) {
        int idx = t + i * 128;          // 0..511
        int r   = idx >> 4;
        int cc  = (idx & 15) * 16;
        cp16(sb + VH_O + r * 272 + cc, (const char*)(vph + (size_t)(kp0 + r) * HDIM) + cc);
        cp16(sb + VL_O + r * 272 + cc, (const char*)(vpl + (size_t)(kp0 + r) * HDIM) + cc);
    }
}

__global__ void __launch_bounds__(128, 3) attn_kernel()
{
    extern __shared__ unsigned char smraw[];
    const uint32_t sb = smem_u32(smraw);

    const int tid  = threadIdx.x;
    const int lane = tid & 31;
    const int w    = tid >> 5;
    const int g    = lane >> 2;
    const int tg   = lane & 3;
    const int bx   = blockIdx.x;       // 512 blocks, heavy q-tiles first
    const int b    = bx & 7;
    const int half = (bx >> 3) & 1;
    const int qt   = 31 - (bx >> 4);
    const int q0   = qt * 64;
    const int n    = qt + 1;
    const int kb   = half ? (n >> 1) : 0;
    const int ke   = half ? n : (n >> 1);

    const __nv_bfloat16* Khg  = g_kh  + (size_t)b * SEQ * HDIM;
    const __nv_bfloat16* Klg  = g_kl  + (size_t)b * SEQ * HDIM;
    const uint32_t*      Vphg = g_vph + (size_t)b * (SEQ/2) * HDIM;
    const uint32_t*      Vplg = g_vpl + (size_t)b * (SEQ/2) * HDIM;
    const uint32_t*      qh32 = (const uint32_t*)g_qh + (size_t)b * SEQ * 32;
    const uint32_t*      ql32 = (const uint32_t*)g_ql + (size_t)b * SEQ * 32;

    // ---- Q fragments from global (Q pre-scaled by 1/8*log2e) ----
    const int rowq = w * 16 + g;
    const int gr0  = q0 + rowq;
    const int gr1  = gr0 + 8;
    uint32_t qfh[4][4], qfl[4][4];
    {
        int base = (q0 + rowq) * 32;
#pragma unroll
        for (int kk = 0; kk < 4; kk++) {
            int o0 = base + kk * 8 + tg;
            qfh[kk][0] = qh32[o0];
            qfh[kk][1] = qh32[o0 + 8 * 32];
            qfh[kk][2] = qh32[o0 + 4];
            qfh[kk][3] = qh32[o0 + 8 * 32 + 4];
            qfl[kk][0] = ql32[o0];
            qfl[kk][1] = ql32[o0 + 8 * 32];
            qfl[kk][2] = ql32[o0 + 4];
            qfl[kk][3] = ql32[o0 + 8 * 32 + 4];
        }
    }

    float m0 = -1e30f, m1 = -1e30f, l0s = 0.f, l1s = 0.f;
    float o[8][4];
#pragma unroll
    for (int nt = 0; nt < 8; nt++)
#pragma unroll
        for (int r = 0; r < 4; r++) o[nt][r] = 0.f;

    if (kb < ke) {
        // prologue: fill stage for first tile
        fill_kv(sb + (kb & 1) * STG, tid, kb, Khg, Klg, Vphg, Vplg);
        CP_COMMIT();

#pragma unroll 1
        for (int kt = kb; kt < ke; kt++) {
            const int k0 = kt * 64;

            // distance-1 prefetch: fill next tile's stage (freed by the
            // trailing __syncthreads of iteration kt-1)
            if (kt + 1 < ke) {
                fill_kv(sb + ((kt + 1) & 1) * STG, tid, kt + 1, Khg, Klg, Vphg, Vplg);
                CP_COMMIT();
                asm volatile("cp.async.wait_group 1;" ::: "memory");
            } else {
                asm volatile("cp.async.wait_group 0;" ::: "memory");
            }
            __syncthreads();

            const unsigned char* st = smraw + (kt & 1) * STG;
            const uint32_t* KH32 = (const uint32_t*)(st);
            const uint32_t* KL32 = (const uint32_t*)(st + 9216);
            const uint32_t* VPH  = (const uint32_t*)(st + VH_O);
            const uint32_t* VPL  = (const uint32_t*)(st + VL_O);

            // ---- S = Q K^T (softmax scale folded into Q) ----
            float s[8][4];
#pragma unroll
            for (int nt = 0; nt < 8; nt++)
#pragma unroll
                for (int r = 0; r < 4; r++) s[nt][r] = 0.f;

#pragma unroll
            for (int kk = 0; kk < 4; kk++) {
#pragma unroll
                for (int nt = 0; nt < 8; nt++) {
                    int base = (nt * 8 + g) * KP32 + kk * 8 + tg;
                    uint32_t bh0 = KH32[base], bh1 = KH32[base + 4];
                    uint32_t bl0 = KL32[base], bl1 = KL32[base + 4];
                    float* c = s[nt];
                    mma_bf16(c[0], c[1], c[2], c[3], qfh[kk][0], qfh[kk][1], qfh[kk][2], qfh[kk][3], bh0, bh1);
                    mma_bf16(c[0], c[1], c[2], c[3], qfl[kk][0], qfl[kk][1], qfl[kk][2], qfl[kk][3], bh0, bh1);
                    mma_bf16(c[0], c[1], c[2], c[3], qfh[kk][0], qfh[kk][1], qfh[kk][2], qfh[kk][3], bl0, bl1);
                }
            }

            // ---- causal mask (diagonal tile only) ----
            if (kt == qt) {
#pragma unroll
                for (int nt = 0; nt < 8; nt++) {
                    int c0 = k0 + nt * 8 + 2 * tg;
                    if (c0     > gr0) s[nt][0] = -1e30f;
                    if (c0 + 1 > gr0) s[nt][1] = -1e30f;
                    if (c0     > gr1) s[nt][2] = -1e30f;
                    if (c0 + 1 > gr1) s[nt][3] = -1e30f;
                }
            }

            // ---- online softmax ----
            float mA = -1e30f, mB = -1e30f;
#pragma unroll
            for (int nt = 0; nt < 8; nt++) {
                mA = fmaxf(mA, fmaxf(s[nt][0], s[nt][1]));
                mB = fmaxf(mB, fmaxf(s[nt][2], s[nt][3]));
            }
            mA = fmaxf(mA, __shfl_xor_sync(0xffffffffu, mA, 1));
            mA = fmaxf(mA, __shfl_xor_sync(0xffffffffu, mA, 2));
            mB = fmaxf(mB, __shfl_xor_sync(0xffffffffu, mB, 1));
            mB = fmaxf(mB, __shfl_xor_sync(0xffffffffu, mB, 2));
            float mn0 = fmaxf(m0, mA);
            float mn1 = fmaxf(m1, mB);
            float al0 = ex2f(m0 - mn0);
            float al1 = ex2f(m1 - mn1);
            m0 = mn0; m1 = mn1;

            float rs0 = 0.f, rs1 = 0.f;
#pragma unroll
            for (int nt = 0; nt < 8; nt++) {
                float p0 = ex2f(s[nt][0] - mn0);
                float p1 = ex2f(s[nt][1] - mn0);
                float p2 = ex2f(s[nt][2] - mn1);
                float p3 = ex2f(s[nt][3] - mn1);
                rs0 += p0 + p1;
                rs1 += p2 + p3;
                s[nt][0] = p0; s[nt][1] = p1; s[nt][2] = p2; s[nt][3] = p3;
            }
            rs0 += __shfl_xor_sync(0xffffffffu, rs0, 1);
            rs0 += __shfl_xor_sync(0xffffffffu, rs0, 2);
            rs1 += __shfl_xor_sync(0xffffffffu, rs1, 1);
            rs1 += __shfl_xor_sync(0xffffffffu, rs1, 2);
            l0s = l0s * al0 + rs0;
            l1s = l1s * al1 + rs1;

#pragma unroll
            for (int nt = 0; nt < 8; nt++) {
                o[nt][0] *= al0; o[nt][1] *= al0;
                o[nt][2] *= al1; o[nt][3] *= al1;
            }

            // ---- O += P V (P frags packed on the fly; V already resident) ----
#pragma unroll
            for (int kk = 0; kk < 4; kk++) {
                uint32_t ah0, aL0, ah1, aL1, ah2, aL2, ah3, aL3;
                split_pack(s[2*kk  ][0], s[2*kk  ][1], ah0, aL0);
                split_pack(s[2*kk  ][2], s[2*kk  ][3], ah1, aL1);
                split_pack(s[2*kk+1][0], s[2*kk+1][1], ah2, aL2);
                split_pack(s[2*kk+1][2], s[2*kk+1][3], ah3, aL3);
#pragma unroll
                for (int nt = 0; nt < 8; nt++) {
                    int h = nt * 8 + g;
                    uint32_t vb0h = VPH[(kk * 8 + tg) * VPP + h];
                    uint32_t vb1h = VPH[(kk * 8 + 4 + tg) * VPP + h];
                    uint32_t vb0l = VPL[(kk * 8 + tg) * VPP + h];
                    uint32_t vb1l = VPL[(kk * 8 + 4 + tg) * VPP + h];
                    float* c = o[nt];
                    mma_bf16(c[0], c[1], c[2], c[3], ah0, ah1, ah2, ah3, vb0h, vb1h);
                    mma_bf16(c[0], c[1], c[2], c[3], aL0, aL1, aL2, aL3, vb0h, vb1h);
                    mma_bf16(c[0], c[1], c[2], c[3], ah0, ah1, ah2, ah3, vb0l, vb1l);
                }
            }
            __syncthreads();   // release stage[kt&1] before next iter's prefetch
        }
    }

    // ---- epilogue: store unnormalized partials ----
    float* po = g_po[half];
    size_t ro0 = ((size_t)b * SEQ + gr0) * HDIM;
    size_t ro1 = ((size_t)b * SEQ + gr1) * HDIM;
#pragma unroll
    for (int nt = 0; nt < 8; nt++) {
        int c = nt * 8 + 2 * tg;
        *(float2*)&po[ro0 + c] = make_float2(o[nt][0], o[nt][1]);
        *(float2*)&po[ro1 + c] = make_float2(o[nt][2], o[nt][3]);
    }
    if (tg == 0) {
        g_pm[half][b * SEQ + gr0] = m0;
        g_pm[half][b * SEQ + gr1] = m1;
        g_pl[half][b * SEQ + gr0] = l0s;
        g_pl[half][b * SEQ + gr1] = l1s;
    }
}

// ---------------------------------------------------------------------------
// Kernel 3: merge split-K partials, normalize, write output. MLP ~10.
// Each thread: 4 float4 per partial (quarter of a 64-float row).
// ---------------------------------------------------------------------------
__global__ void __launch_bounds__(256) merge_kernel(float* __restrict__ out)
{
    int idx  = blockIdx.x * 256 + threadIdx.x;      // 0..65535 quarter-rows
    int row  = idx >> 2;
    int base = idx * 4;                             // float4 index

    float ma = g_pm[0][row], mb = g_pm[1][row];
    float la = g_pl[0][row], lb = g_pl[1][row];

    float4 a[4], c[4];
#pragma unroll
    for (int i = 0; i < 4; i++) a[i] = ((const float4*)g_po[0])[base + i];
#pragma unroll
    for (int i = 0; i < 4; i++) c[i] = ((const float4*)g_po[1])[base + i];

    float ms  = fmaxf(ma, mb);
    float sa  = ex2f(ma - ms);
    float sc  = ex2f(mb - ms);
    float inv = 1.f / (la * sa + lb * sc);
    sa *= inv;
    sc *= inv;

#pragma unroll
    for (int i = 0; i < 4; i++) {
        float4 r;
        r.x = a[i].x * sa + c[i].x * sc;
        r.y = a[i].y * sa + c[i].y * sc;
        r.z = a[i].z * sa + c[i].z * sc;
        r.w = a[i].w * sa + c[i].w * sc;
        ((float4*)out)[base + i] = r;
    }
}

// ---------------------------------------------------------------------------
extern "C" void kernel_launch(void* const* d_in, const int* in_sizes, int n_in,
                              void* d_out, int out_size)
{
    const float* x  = (const float*)d_in[0];
    const float* wk = (const float*)d_in[1];
    const float* wq = (const float*)d_in[2];
    const float* wv = (const float*)d_in[3];
    float* out = (float*)d_out;

    prep_w<<<384, 256>>>(wk, wq, wv);

    cudaFuncSetAttribute(proj_kernel,
                         cudaFuncAttributeMaxDynamicSharedMemorySize, PROJ_SMEM);
    proj_kernel<<<MTOT / 128, 256, PROJ_SMEM>>>(x);

    cudaFuncSetAttribute(attn_kernel,
                         cudaFuncAttributeMaxDynamicSharedMemorySize, ATTN_SMEM);
    attn_kernel<<<512, 128, ATTN_SMEM>>>();

    merge_kernel<<<256, 256>>>(out);
}

// round 12
// speedup vs baseline: 1.0155x; 1.0155x over previous
#include <cuda_runtime.h>
#include <cuda_bf16.h>
#include <cuda_fp16.h>
#include <stdint.h>

#define BATCH 8
#define SEQ   2048
#define EDIM  1024
#define HDIM  64
#define MTOT  (BATCH*SEQ)

// scratch (device globals: no allocation allowed)
__device__ uint32_t       g_qh [MTOT*32], g_ql [MTOT*32];   // Q fp16 hi/lo (pairs)
__device__ uint32_t       g_k16[MTOT*32];                   // K fp16 (pairs)
__device__ uint32_t       g_vph[(MTOT/2)*HDIM], g_vpl[(MTOT/2)*HDIM]; // V fp16 hi/lo, k-pair packed
__device__ uint32_t       g_wph[512*192],       g_wpl[512*192];
__device__ float          g_po[2][MTOT*HDIM];   // split-K partial O
__device__ float          g_pm[2][MTOT];        // partial row max (log2 domain)
__device__ float          g_pl[2][MTOT];        // partial row sum

// ---------------------------------------------------------------------------
// helpers
// ---------------------------------------------------------------------------
__device__ __forceinline__ void mma_bf16(float& d0, float& d1, float& d2, float& d3,
                                         uint32_t a0, uint32_t a1, uint32_t a2, uint32_t a3,
                                         uint32_t b0, uint32_t b1)
{
    asm("mma.sync.aligned.m16n8k16.row.col.f32.bf16.bf16.f32 "
        "{%0,%1,%2,%3},{%4,%5,%6,%7},{%8,%9},{%0,%1,%2,%3};"
        : "+f"(d0), "+f"(d1), "+f"(d2), "+f"(d3)
        : "r"(a0), "r"(a1), "r"(a2), "r"(a3), "r"(b0), "r"(b1));
}

__device__ __forceinline__ void mma_f16(float& d0, float& d1, float& d2, float& d3,
                                        uint32_t a0, uint32_t a1, uint32_t a2, uint32_t a3,
                                        uint32_t b0, uint32_t b1)
{
    asm("mma.sync.aligned.m16n8k16.row.col.f32.f16.f16.f32 "
        "{%0,%1,%2,%3},{%4,%5,%6,%7},{%8,%9},{%0,%1,%2,%3};"
        : "+f"(d0), "+f"(d1), "+f"(d2), "+f"(d3)
        : "r"(a0), "r"(a1), "r"(a2), "r"(a3), "r"(b0), "r"(b1));
}

// bf16 split (projection path)
__device__ __forceinline__ void split2(float x, __nv_bfloat16& h, __nv_bfloat16& l)
{
    h = __float2bfloat16(x);
    l = __float2bfloat16(x - __bfloat162float(h));
}
__device__ __forceinline__ void split_pack(float x0, float x1, uint32_t& hp, uint32_t& lp)
{
    __nv_bfloat16 h0, l0, h1, l1;
    split2(x0, h0, l0);
    split2(x1, h1, l1);
    __nv_bfloat162 hh = __halves2bfloat162(h0, h1);
    __nv_bfloat162 ll = __halves2bfloat162(l0, l1);
    hp = *reinterpret_cast<uint32_t*>(&hh);
    lp = *reinterpret_cast<uint32_t*>(&ll);
}

// fp16 split/pack (attention path)
__device__ __forceinline__ void split2h(float x, __half& h, __half& l)
{
    h = __float2half(x);
    l = __float2half(x - __half2float(h));
}
__device__ __forceinline__ void split_pack16(float x0, float x1, uint32_t& hp, uint32_t& lp)
{
    __half h0, l0, h1, l1;
    split2h(x0, h0, l0);
    split2h(x1, h1, l1);
    __half2 hh = __halves2half2(h0, h1);
    __half2 ll = __halves2half2(l0, l1);
    hp = *reinterpret_cast<uint32_t*>(&hh);
    lp = *reinterpret_cast<uint32_t*>(&ll);
}
__device__ __forceinline__ uint32_t pack_h16(float x0, float x1)
{
    __half2 hh = __halves2half2(__float2half(x0), __float2half(x1));
    return *reinterpret_cast<uint32_t*>(&hh);
}

__device__ __forceinline__ float ex2f(float x)
{
    float y;
    asm("ex2.approx.f32 %0, %1;" : "=f"(y) : "f"(x));
    return y;
}

__device__ __forceinline__ void cp16(uint32_t dst, const void* src)
{
    asm volatile("cp.async.cg.shared.global [%0], [%1], 16;" :: "r"(dst), "l"(src));
}
__device__ __forceinline__ uint32_t smem_u32(const void* p)
{
    uint32_t a;
    asm("{ .reg .u64 t; cvta.to.shared.u64 t, %1; cvt.u32.u64 %0, t; }" : "=r"(a) : "l"(p));
    return a;
}
#define CP_COMMIT() asm volatile("cp.async.commit_group;" ::: "memory")

// ---------------------------------------------------------------------------
// prep kernel: pack W (k-pair hi/lo bf16 u32) — projection path unchanged
// ---------------------------------------------------------------------------
__global__ void prep_w(const float* __restrict__ wk, const float* __restrict__ wq,
                       const float* __restrict__ wv)
{
    int idx = blockIdx.x * 256 + threadIdx.x;       // 512*192 = 98304
    int kp = idx / 192, c = idx - kp * 192;
    const float* wp = (c < 64) ? wk : ((c < 128) ? wq : wv);
    int cc = c & 63;
    float w0 = wp[(2 * kp)     * HDIM + cc];
    float w1 = wp[(2 * kp + 1) * HDIM + cc];
    uint32_t hp, lp;
    split_pack(w0, w1, hp, lp);
    g_wph[idx] = hp;
    g_wpl[idx] = lp;
}

// ---------------------------------------------------------------------------
// Kernel 1: fused QKV projection, HMMA bf16 3-term split (proven, unchanged
// mainloop). Epilogue now emits fp16: K single, Q scaled hi/lo, V hi/lo pairs.
// ---------------------------------------------------------------------------
#define AP   40
#define BP   200
#define XH_OFF 0
#define XL_OFF 20480
#define WH_OFF 40960
#define WL_OFF 66560
#define PROJ_SMEM 92160

__global__ void __launch_bounds__(256) proj_kernel(const float* __restrict__ x)
{
    extern __shared__ unsigned char sm[];
    const uint32_t smb = smem_u32(sm);

    const int tid   = threadIdx.x;
    const int lane  = tid & 31;
    const int warp  = tid >> 5;
    const int warpM = warp >> 2;
    const int warpN = warp & 3;
    const int g     = lane >> 2;
    const int tg    = lane & 3;
    const int row0  = blockIdx.x * 128;

    float acc[4][6][4];
#pragma unroll
    for (int i = 0; i < 4; i++)
#pragma unroll
        for (int j = 0; j < 6; j++)
#pragma unroll
            for (int r = 0; r < 4; r++) acc[i][j][r] = 0.f;

    float4 xr[4];
    int xrr[4], xcc[4];
#pragma unroll
    for (int l = 0; l < 4; l++) {
        int idx = tid + l * 256;
        xrr[l] = idx >> 3;
        xcc[l] = (idx & 7) << 2;
    }

#pragma unroll
    for (int l = 0; l < 4; l++)
        xr[l] = *(const float4*)&x[(size_t)(row0 + xrr[l]) * EDIM + xcc[l]];
    {
        __nv_bfloat16* XH = (__nv_bfloat16*)(sm + XH_OFF);
        __nv_bfloat16* XL = (__nv_bfloat16*)(sm + XL_OFF);
#pragma unroll
        for (int l = 0; l < 4; l++) {
            __nv_bfloat16 h0,l0,h1,l1,h2,l2,h3,l3;
            split2(xr[l].x, h0, l0); split2(xr[l].y, h1, l1);
            split2(xr[l].z, h2, l2); split2(xr[l].w, h3, l3);
            int base = xrr[l] * AP + xcc[l];
            *(__nv_bfloat162*)&XH[base]     = __halves2bfloat162(h0, h1);
            *(__nv_bfloat162*)&XH[base + 2] = __halves2bfloat162(h2, h3);
            *(__nv_bfloat162*)&XL[base]     = __halves2bfloat162(l0, l1);
            *(__nv_bfloat162*)&XL[base + 2] = __halves2bfloat162(l2, l3);
        }
    }
#pragma unroll
    for (int i = 0; i < 3; i++) {
        int idx = tid + i * 256;
        int r   = idx / 48;
        int cc  = idx - r * 48;
        cp16(smb + WH_OFF + r * (BP*4) + cc * 16, (const char*)(g_wph + (size_t)r * 192) + cc * 16);
        cp16(smb + WL_OFF + r * (BP*4) + cc * 16, (const char*)(g_wpl + (size_t)r * 192) + cc * 16);
    }
    CP_COMMIT();

#pragma unroll 1
    for (int k = 0; k < 32; k++) {
        const int buf = k & 1;
        if (k < 31) {
            const int k0n = (k + 1) * 32;
#pragma unroll
            for (int l = 0; l < 4; l++)
                xr[l] = *(const float4*)&x[(size_t)(row0 + xrr[l]) * EDIM + k0n + xcc[l]];
            const int kp0 = k0n >> 1;
            const uint32_t wdst = smb + ((k + 1) & 1) * 12800;
#pragma unroll
            for (int i = 0; i < 3; i++) {
                int idx = tid + i * 256;
                int r   = idx / 48;
                int cc  = idx - r * 48;
                cp16(wdst + WH_OFF + r * (BP*4) + cc * 16, (const char*)(g_wph + (size_t)(kp0 + r) * 192) + cc * 16);
                cp16(wdst + WL_OFF + r * (BP*4) + cc * 16, (const char*)(g_wpl + (size_t)(kp0 + r) * 192) + cc * 16);
            }
            CP_COMMIT();
            asm volatile("cp.async.wait_group 1;" ::: "memory");
        } else {
            asm volatile("cp.async.wait_group 0;" ::: "memory");
        }
        __syncthreads();

        const uint32_t* Ah32 = (const uint32_t*)(sm + XH_OFF + buf * 10240);
        const uint32_t* Al32 = (const uint32_t*)(sm + XL_OFF + buf * 10240);
        const uint32_t* Bh   = (const uint32_t*)(sm + WH_OFF + buf * 12800);
        const uint32_t* Bl   = (const uint32_t*)(sm + WL_OFF + buf * 12800);
        const int ap32 = AP / 2;

#pragma unroll
        for (int k16 = 0; k16 < 2; k16++) {
            uint32_t ah[4][4], al[4][4];
#pragma unroll
            for (int mt = 0; mt < 4; mt++) {
                int rb = (warpM * 64 + mt * 16 + g) * ap32 + k16 * 8 + tg;
                ah[mt][0] = Ah32[rb];
                ah[mt][1] = Ah32[rb + 8 * ap32];
                ah[mt][2] = Ah32[rb + 4];
                ah[mt][3] = Ah32[rb + 8 * ap32 + 4];
                al[mt][0] = Al32[rb];
                al[mt][1] = Al32[rb + 8 * ap32];
                al[mt][2] = Al32[rb + 4];
                al[mt][3] = Al32[rb + 8 * ap32 + 4];
            }
#pragma unroll
            for (int nt = 0; nt < 6; nt++) {
                int n  = warpN * 48 + nt * 8 + g;
                int kp = k16 * 8 + tg;
                uint32_t bh0 = Bh[kp * BP + n], bh1 = Bh[(kp + 4) * BP + n];
                uint32_t bl0 = Bl[kp * BP + n], bl1 = Bl[(kp + 4) * BP + n];
#pragma unroll
                for (int mt = 0; mt < 4; mt++) {
                    float* c = acc[mt][nt];
                    mma_bf16(c[0], c[1], c[2], c[3], ah[mt][0], ah[mt][1], ah[mt][2], ah[mt][3], bh0, bh1);
                    mma_bf16(c[0], c[1], c[2], c[3], al[mt][0], al[mt][1], al[mt][2], al[mt][3], bh0, bh1);
                    mma_bf16(c[0], c[1], c[2], c[3], ah[mt][0], ah[mt][1], ah[mt][2], ah[mt][3], bl0, bl1);
                }
            }
        }

        if (k < 31) {
            __nv_bfloat16* XH = (__nv_bfloat16*)(sm + XH_OFF + ((k + 1) & 1) * 10240);
            __nv_bfloat16* XL = (__nv_bfloat16*)(sm + XL_OFF + ((k + 1) & 1) * 10240);
#pragma unroll
            for (int l = 0; l < 4; l++) {
                __nv_bfloat16 h0,l0,h1,l1,h2,l2,h3,l3;
                split2(xr[l].x, h0, l0); split2(xr[l].y, h1, l1);
                split2(xr[l].z, h2, l2); split2(xr[l].w, h3, l3);
                int base = xrr[l] * AP + xcc[l];
                *(__nv_bfloat162*)&XH[base]     = __halves2bfloat162(h0, h1);
                *(__nv_bfloat162*)&XH[base + 2] = __halves2bfloat162(h2, h3);
                *(__nv_bfloat162*)&XL[base]     = __halves2bfloat162(l0, l1);
                *(__nv_bfloat162*)&XL[base + 2] = __halves2bfloat162(l2, l3);
            }
        }
        __syncthreads();
    }

    // ---- epilogue: K fp16 single, Q fp16 scaled hi/lo, V fp16 hi/lo pairs ----
    const float CQ = 0.125f * 1.44269504088896340736f;   // 1/sqrt(H) * log2(e)
#pragma unroll
    for (int mt = 0; mt < 4; mt++) {
#pragma unroll
        for (int nt = 0; nt < 6; nt++) {
            int gcol = warpN * 48 + nt * 8 + 2 * tg;
            int seg  = gcol >> 6;
            int cc   = gcol & 63;
            int r0   = row0 + warpM * 64 + mt * 16 + g;
            float* c = acc[mt][nt];
            if (seg == 2) {
                // V: pair adjacent seq rows (g even <-> g odd) via shfl, fp16 hi/lo
                float p0 = __shfl_xor_sync(0xffffffffu, c[0], 4);
                float p1 = __shfl_xor_sync(0xffffffffu, c[1], 4);
                float p2 = __shfl_xor_sync(0xffffffffu, c[2], 4);
                float p3 = __shfl_xor_sync(0xffffffffu, c[3], 4);
                if ((g & 1) == 0) {
                    uint32_t h0, l0, h1, l1;
                    split_pack16(c[0], p0, h0, l0);
                    split_pack16(c[1], p1, h1, l1);
                    int kp = r0 >> 1;
                    *(uint2*)&g_vph[kp * 64 + cc] = make_uint2(h0, h1);
                    *(uint2*)&g_vpl[kp * 64 + cc] = make_uint2(l0, l1);
                    split_pack16(c[2], p2, h0, l0);
                    split_pack16(c[3], p3, h1, l1);
                    int kp2 = (r0 + 8) >> 1;
                    *(uint2*)&g_vph[kp2 * 64 + cc] = make_uint2(h0, h1);
                    *(uint2*)&g_vpl[kp2 * 64 + cc] = make_uint2(l0, l1);
                }
            } else if (seg == 0) {
                // K: single fp16
                g_k16[r0 * 32 + cc / 2]       = pack_h16(c[0], c[1]);
                g_k16[(r0 + 8) * 32 + cc / 2] = pack_h16(c[2], c[3]);
            } else {
                // Q: scaled, fp16 hi/lo
                uint32_t hp, lp;
                split_pack16(c[0] * CQ, c[1] * CQ, hp, lp);
                g_qh[r0 * 32 + cc / 2] = hp;
                g_ql[r0 * 32 + cc / 2] = lp;
                split_pack16(c[2] * CQ, c[3] * CQ, hp, lp);
                g_qh[(r0 + 8) * 32 + cc / 2] = hp;
                g_ql[(r0 + 8) * 32 + cc / 2] = lp;
            }
        }
    }
}

// ---------------------------------------------------------------------------
// Kernel 2: causal flash attention, block-level split-K partials, fp16.
// QK = (Qh + Ql) * K      (Q 2-term fp16, K single fp16)  -> 64 MMAs/tile
// PV = P * (Vh + Vl)      (P single fp16, V 2-term fp16)  -> 64 MMAs/tile
// Stage = K 9216 + VH 8704 + VL 8704 = 26624 -> 4 blocks/SM, 1 wave.
// ---------------------------------------------------------------------------
#define KP32   36                       // K smem pitch (u32), rows 144B
#define VPP    68                       // V smem pitch (u32), rows 272B
#define STG    26624
#define VH_O   9216
#define VL_O   17920
#define ATTN_SMEM (2*STG)               // 53248; 4 blocks/SM = 212992

__device__ __forceinline__ void fill_kv(uint32_t sb, int t, int kt,
                                        const uint32_t* k16,
                                        const uint32_t* vph, const uint32_t* vpl)
{
    const int k0  = kt * 64;
    const int kp0 = k0 >> 1;
#pragma unroll
    for (int i = 0; i < 4; i++) {
        int idx = t + i * 128;          // 0..511
        int r   = idx >> 3;
        int cc  = (idx & 7) * 16;
        cp16(sb + r * 144 + cc, (const char*)(k16 + (size_t)(k0 + r) * 32) + cc);
    }
#pragma unroll
    for (int i = 0; i < 4; i++) {
        int idx = t + i * 128;          // 0..511
        int r   = idx >> 4;
        int cc  = (idx & 15) * 16;
        cp16(sb + VH_O + r * 272 + cc, (const char*)(vph + (size_t)(kp0 + r) * HDIM) + cc);
        cp16(sb + VL_O + r * 272 + cc, (const char*)(vpl + (size_t)(kp0 + r) * HDIM) + cc);
    }
}

__global__ void __launch_bounds__(128, 4) attn_kernel()
{
    extern __shared__ unsigned char smraw[];
    const uint32_t sb = smem_u32(smraw);

    const int tid  = threadIdx.x;
    const int lane = tid & 31;
    const int w    = tid >> 5;
    const int g    = lane >> 2;
    const int tg   = lane & 3;
    const int bx   = blockIdx.x;       // 512 blocks, heavy q-tiles first
    const int b    = bx & 7;
    const int half = (bx >> 3) & 1;
    const int qt   = 31 - (bx >> 4);
    const int q0   = qt * 64;
    const int n    = qt + 1;
    const int kb   = half ? (n >> 1) : 0;
    const int ke   = half ? n : (n >> 1);

    const uint32_t* K16g = g_k16 + (size_t)b * SEQ * 32;
    const uint32_t* Vphg = g_vph + (size_t)b * (SEQ/2) * HDIM;
    const uint32_t* Vplg = g_vpl + (size_t)b * (SEQ/2) * HDIM;
    const uint32_t* qh32 = g_qh + (size_t)b * SEQ * 32;
    const uint32_t* ql32 = g_ql + (size_t)b * SEQ * 32;

    // ---- Q fragments from global (fp16 hi/lo, pre-scaled) ----
    const int rowq = w * 16 + g;
    const int gr0  = q0 + rowq;
    const int gr1  = gr0 + 8;
    uint32_t qfh[4][4], qfl[4][4];
    {
        int base = (q0 + rowq) * 32;
#pragma unroll
        for (int kk = 0; kk < 4; kk++) {
            int o0 = base + kk * 8 + tg;
            qfh[kk][0] = qh32[o0];
            qfh[kk][1] = qh32[o0 + 8 * 32];
            qfh[kk][2] = qh32[o0 + 4];
            qfh[kk][3] = qh32[o0 + 8 * 32 + 4];
            qfl[kk][0] = ql32[o0];
            qfl[kk][1] = ql32[o0 + 8 * 32];
            qfl[kk][2] = ql32[o0 + 4];
            qfl[kk][3] = ql32[o0 + 8 * 32 + 4];
        }
    }

    float m0 = -1e30f, m1 = -1e30f, l0s = 0.f, l1s = 0.f;
    float o[8][4];
#pragma unroll
    for (int nt = 0; nt < 8; nt++)
#pragma unroll
        for (int r = 0; r < 4; r++) o[nt][r] = 0.f;

    if (kb < ke) {
        fill_kv(sb + (kb & 1) * STG, tid, kb, K16g, Vphg, Vplg);
        CP_COMMIT();

#pragma unroll 1
        for (int kt = kb; kt < ke; kt++) {
            const int k0 = kt * 64;

            if (kt + 1 < ke) {
                fill_kv(sb + ((kt + 1) & 1) * STG, tid, kt + 1, K16g, Vphg, Vplg);
                CP_COMMIT();
                asm volatile("cp.async.wait_group 1;" ::: "memory");
            } else {
                asm volatile("cp.async.wait_group 0;" ::: "memory");
            }
            __syncthreads();

            const unsigned char* st = smraw + (kt & 1) * STG;
            const uint32_t* KH32 = (const uint32_t*)(st);
            const uint32_t* VPH  = (const uint32_t*)(st + VH_O);
            const uint32_t* VPL  = (const uint32_t*)(st + VL_O);

            // ---- S = Q K^T (Qh*K + Ql*K) ----
            float s[8][4];
#pragma unroll
            for (int nt = 0; nt < 8; nt++)
#pragma unroll
                for (int r = 0; r < 4; r++) s[nt][r] = 0.f;

#pragma unroll
            for (int kk = 0; kk < 4; kk++) {
#pragma unroll
                for (int nt = 0; nt < 8; nt++) {
                    int base = (nt * 8 + g) * KP32 + kk * 8 + tg;
                    uint32_t bh0 = KH32[base], bh1 = KH32[base + 4];
                    float* c = s[nt];
                    mma_f16(c[0], c[1], c[2], c[3], qfh[kk][0], qfh[kk][1], qfh[kk][2], qfh[kk][3], bh0, bh1);
                    mma_f16(c[0], c[1], c[2], c[3], qfl[kk][0], qfl[kk][1], qfl[kk][2], qfl[kk][3], bh0, bh1);
                }
            }

            // ---- causal mask (diagonal tile only) ----
            if (kt == qt) {
#pragma unroll
                for (int nt = 0; nt < 8; nt++) {
                    int c0 = k0 + nt * 8 + 2 * tg;
                    if (c0     > gr0) s[nt][0] = -1e30f;
                    if (c0 + 1 > gr0) s[nt][1] = -1e30f;
                    if (c0     > gr1) s[nt][2] = -1e30f;
                    if (c0 + 1 > gr1) s[nt][3] = -1e30f;
                }
            }

            // ---- online softmax ----
            float mA = -1e30f, mB = -1e30f;
#pragma unroll
            for (int nt = 0; nt < 8; nt++) {
                mA = fmaxf(mA, fmaxf(s[nt][0], s[nt][1]));
                mB = fmaxf(mB, fmaxf(s[nt][2], s[nt][3]));
            }
            mA = fmaxf(mA, __shfl_xor_sync(0xffffffffu, mA, 1));
            mA = fmaxf(mA, __shfl_xor_sync(0xffffffffu, mA, 2));
            mB = fmaxf(mB, __shfl_xor_sync(0xffffffffu, mB, 1));
            mB = fmaxf(mB, __shfl_xor_sync(0xffffffffu, mB, 2));
            float mn0 = fmaxf(m0, mA);
            float mn1 = fmaxf(m1, mB);
            float al0 = ex2f(m0 - mn0);
            float al1 = ex2f(m1 - mn1);
            m0 = mn0; m1 = mn1;

            float rs0 = 0.f, rs1 = 0.f;
#pragma unroll
            for (int nt = 0; nt < 8; nt++) {
                float p0 = ex2f(s[nt][0] - mn0);
                float p1 = ex2f(s[nt][1] - mn0);
                float p2 = ex2f(s[nt][2] - mn1);
                float p3 = ex2f(s[nt][3] - mn1);
                rs0 += p0 + p1;
                rs1 += p2 + p3;
                s[nt][0] = p0; s[nt][1] = p1; s[nt][2] = p2; s[nt][3] = p3;
            }
            rs0 += __shfl_xor_sync(0xffffffffu, rs0, 1);
            rs0 += __shfl_xor_sync(0xffffffffu, rs0, 2);
            rs1 += __shfl_xor_sync(0xffffffffu, rs1, 1);
            rs1 += __shfl_xor_sync(0xffffffffu, rs1, 2);
            l0s = l0s * al0 + rs0;
            l1s = l1s * al1 + rs1;

#pragma unroll
            for (int nt = 0; nt < 8; nt++) {
                o[nt][0] *= al0; o[nt][1] *= al0;
                o[nt][2] *= al1; o[nt][3] *= al1;
            }

            // ---- O += P V (P fp16 single; V hi + lo) ----
#pragma unroll
            for (int kk = 0; kk < 4; kk++) {
                uint32_t ah0 = pack_h16(s[2*kk  ][0], s[2*kk  ][1]);
                uint32_t ah1 = pack_h16(s[2*kk  ][2], s[2*kk  ][3]);
                uint32_t ah2 = pack_h16(s[2*kk+1][0], s[2*kk+1][1]);
                uint32_t ah3 = pack_h16(s[2*kk+1][2], s[2*kk+1][3]);
#pragma unroll
                for (int nt = 0; nt < 8; nt++) {
                    int h = nt * 8 + g;
                    uint32_t vb0h = VPH[(kk * 8 + tg) * VPP + h];
                    uint32_t vb1h = VPH[(kk * 8 + 4 + tg) * VPP + h];
                    uint32_t vb0l = VPL[(kk * 8 + tg) * VPP + h];
                    uint32_t vb1l = VPL[(kk * 8 + 4 + tg) * VPP + h];
                    float* c = o[nt];
                    mma_f16(c[0], c[1], c[2], c[3], ah0, ah1, ah2, ah3, vb0h, vb1h);
                    mma_f16(c[0], c[1], c[2], c[3], ah0, ah1, ah2, ah3, vb0l, vb1l);
                }
            }
            __syncthreads();   // release stage[kt&1] before next iter's prefetch
        }
    }

    // ---- epilogue: store unnormalized partials ----
    float* po = g_po[half];
    size_t ro0 = ((size_t)b * SEQ + gr0) * HDIM;
    size_t ro1 = ((size_t)b * SEQ + gr1) * HDIM;
#pragma unroll
    for (int nt = 0; nt < 8; nt++) {
        int c = nt * 8 + 2 * tg;
        *(float2*)&po[ro0 + c] = make_float2(o[nt][0], o[nt][1]);
        *(float2*)&po[ro1 + c] = make_float2(o[nt][2], o[nt][3]);
    }
    if (tg == 0) {
        g_pm[half][b * SEQ + gr0] = m0;
        g_pm[half][b * SEQ + gr1] = m1;
        g_pl[half][b * SEQ + gr0] = l0s;
        g_pl[half][b * SEQ + gr1] = l1s;
    }
}

// ---------------------------------------------------------------------------
// Kernel 3: merge split-K partials (proven version, unchanged).
// ---------------------------------------------------------------------------
__global__ void __launch_bounds__(256) merge_kernel(float* __restrict__ out)
{
    int idx  = blockIdx.x * 256 + threadIdx.x;
    int row  = idx >> 2;
    int base = idx * 4;

    float ma = g_pm[0][row], mb = g_pm[1][row];
    float la = g_pl[0][row], lb = g_pl[1][row];

    float4 a[4], c[4];
#pragma unroll
    for (int i = 0; i < 4; i++) a[i] = ((const float4*)g_po[0])[base + i];
#pragma unroll
    for (int i = 0; i < 4; i++) c[i] = ((const float4*)g_po[1])[base + i];

    float ms  = fmaxf(ma, mb);
    float sa  = ex2f(ma - ms);
    float sc  = ex2f(mb - ms);
    float inv = 1.f / (la * sa + lb * sc);
    sa *= inv;
    sc *= inv;

#pragma unroll
    for (int i = 0; i < 4; i++) {
        float4 r;
        r.x = a[i].x * sa + c[i].x * sc;
        r.y = a[i].y * sa + c[i].y * sc;
        r.z = a[i].z * sa + c[i].z * sc;
        r.w = a[i].w * sa + c[i].w * sc;
        ((float4*)out)[base + i] = r;
    }
}

// ---------------------------------------------------------------------------
extern "C" void kernel_launch(void* const* d_in, const int* in_sizes, int n_in,
                              void* d_out, int out_size)
{
    const float* x  = (const float*)d_in[0];
    const float* wk = (const float*)d_in[1];
    const float* wq = (const float*)d_in[2];
    const float* wv = (const float*)d_in[3];
    float* out = (float*)d_out;

    prep_w<<<384, 256>>>(wk, wq, wv);

    cudaFuncSetAttribute(proj_kernel,
                         cudaFuncAttributeMaxDynamicSharedMemorySize, PROJ_SMEM);
    proj_kernel<<<MTOT / 128, 256, PROJ_SMEM>>>(x);

    cudaFuncSetAttribute(attn_kernel,
                         cudaFuncAttributeMaxDynamicSharedMemorySize, ATTN_SMEM);
    attn_kernel<<<512, 128, ATTN_SMEM>>>();

    merge_kernel<<<256, 256>>>(out);
}

// round 17
// speedup vs baseline: 1.2034x; 1.1850x over previous
#include <cuda_runtime.h>
#include <cuda_bf16.h>
#include <cuda_fp16.h>
#include <stdint.h>

#define BATCH 8
#define SEQ   2048
#define EDIM  1024
#define HDIM  64
#define MTOT  (BATCH*SEQ)

// scratch (device globals: no allocation allowed)
__device__ uint32_t       g_qh [MTOT*32], g_ql [MTOT*32];   // Q fp16 hi/lo (pairs)
__device__ uint32_t       g_k16[MTOT*32];                   // K fp16 (pairs)
__device__ uint32_t       g_vph[(MTOT/2)*HDIM], g_vpl[(MTOT/2)*HDIM]; // V fp16 hi/lo, k-pair packed
__device__ uint32_t       g_wp16[512*192];                  // W fp16 single (k-pair packed)
__device__ float          g_po[2][MTOT*HDIM];   // split-K partial O
__device__ float          g_pm[2][MTOT];        // partial row max (log2 domain)
__device__ float          g_pl[2][MTOT];        // partial row sum

// ---------------------------------------------------------------------------
// helpers
// ---------------------------------------------------------------------------
__device__ __forceinline__ void mma_f16(float& d0, float& d1, float& d2, float& d3,
                                        uint32_t a0, uint32_t a1, uint32_t a2, uint32_t a3,
                                        uint32_t b0, uint32_t b1)
{
    asm("mma.sync.aligned.m16n8k16.row.col.f32.f16.f16.f32 "
        "{%0,%1,%2,%3},{%4,%5,%6,%7},{%8,%9},{%0,%1,%2,%3};"
        : "+f"(d0), "+f"(d1), "+f"(d2), "+f"(d3)
        : "r"(a0), "r"(a1), "r"(a2), "r"(a3), "r"(b0), "r"(b1));
}

// fp16 split/pack
__device__ __forceinline__ void split2h(float x, __half& h, __half& l)
{
    h = __float2half(x);
    l = __float2half(x - __half2float(h));
}
__device__ __forceinline__ void split_pack16(float x0, float x1, uint32_t& hp, uint32_t& lp)
{
    __half h0, l0, h1, l1;
    split2h(x0, h0, l0);
    split2h(x1, h1, l1);
    __half2 hh = __halves2half2(h0, h1);
    __half2 ll = __halves2half2(l0, l1);
    hp = *reinterpret_cast<uint32_t*>(&hh);
    lp = *reinterpret_cast<uint32_t*>(&ll);
}
__device__ __forceinline__ uint32_t pack_h16(float x0, float x1)
{
    __half2 hh = __halves2half2(__float2half(x0), __float2half(x1));
    return *reinterpret_cast<uint32_t*>(&hh);
}

__device__ __forceinline__ float ex2f(float x)
{
    float y;
    asm("ex2.approx.f32 %0, %1;" : "=f"(y) : "f"(x));
    return y;
}

__device__ __forceinline__ void cp16(uint32_t dst, const void* src)
{
    asm volatile("cp.async.cg.shared.global [%0], [%1], 16;" :: "r"(dst), "l"(src));
}
__device__ __forceinline__ uint32_t smem_u32(const void* p)
{
    uint32_t a;
    asm("{ .reg .u64 t; cvta.to.shared.u64 t, %1; cvt.u32.u64 %0, t; }" : "=r"(a) : "l"(p));
    return a;
}
#define CP_COMMIT() asm volatile("cp.async.commit_group;" ::: "memory")

// ---------------------------------------------------------------------------
// prep kernel: pack W (k-pair fp16 single u32)
// ---------------------------------------------------------------------------
__global__ void prep_w(const float* __restrict__ wk, const float* __restrict__ wq,
                       const float* __restrict__ wv)
{
    int idx = blockIdx.x * 256 + threadIdx.x;       // 512*192 = 98304
    int kp = idx / 192, c = idx - kp * 192;
    const float* wp = (c < 64) ? wk : ((c < 128) ? wq : wv);
    int cc = c & 63;
    float w0 = wp[(2 * kp)     * HDIM + cc];
    float w1 = wp[(2 * kp + 1) * HDIM + cc];
    g_wp16[idx] = pack_h16(w0, w1);
}

// ---------------------------------------------------------------------------
// Kernel 1: fused QKV projection, HMMA fp16 2-term: (Xh + Xl) * W_fp16.
// Block: 128 rows x 192 cols, 256 thr (8 warps = 2m x 4n), K-chunk 32,
// double-buffered. Epilogue: K fp16 single, Q scaled fp16 hi/lo, V fp16
// hi/lo k-pair packed (unchanged from round 12).
// ---------------------------------------------------------------------------
#define AP   40          // X smem pitch (fp16 elements)
#define BP   200         // W smem pitch (u32): bank = 8*tg + g, conflict-free
#define XH_OFF 0         // 2 x 10240
#define XL_OFF 20480     // 2 x 10240
#define W_OFF  40960     // 2 x 12800
#define PROJ_SMEM 66560

__global__ void __launch_bounds__(256) proj_kernel(const float* __restrict__ x)
{
    extern __shared__ unsigned char sm[];
    const uint32_t smb = smem_u32(sm);

    const int tid   = threadIdx.x;
    const int lane  = tid & 31;
    const int warp  = tid >> 5;
    const int warpM = warp >> 2;
    const int warpN = warp & 3;
    const int g     = lane >> 2;
    const int tg    = lane & 3;
    const int row0  = blockIdx.x * 128;

    float acc[4][6][4];
#pragma unroll
    for (int i = 0; i < 4; i++)
#pragma unroll
        for (int j = 0; j < 6; j++)
#pragma unroll
            for (int r = 0; r < 4; r++) acc[i][j][r] = 0.f;

    float4 xr[4];
    int xrr[4], xcc[4];
#pragma unroll
    for (int l = 0; l < 4; l++) {
        int idx = tid + l * 256;
        xrr[l] = idx >> 3;
        xcc[l] = (idx & 7) << 2;
    }

    // ---- prologue: chunk 0 ----
#pragma unroll
    for (int l = 0; l < 4; l++)
        xr[l] = *(const float4*)&x[(size_t)(row0 + xrr[l]) * EDIM + xcc[l]];
    {
        uint32_t* XH = (uint32_t*)(sm + XH_OFF);
        uint32_t* XL = (uint32_t*)(sm + XL_OFF);
#pragma unroll
        for (int l = 0; l < 4; l++) {
            uint32_t h0, l0, h1, l1;
            split_pack16(xr[l].x, xr[l].y, h0, l0);
            split_pack16(xr[l].z, xr[l].w, h1, l1);
            int base = (xrr[l] * AP + xcc[l]) >> 1;   // u32 index
            XH[base]     = h0;
            XH[base + 1] = h1;
            XL[base]     = l0;
            XL[base + 1] = l1;
        }
    }
#pragma unroll
    for (int i = 0; i < 3; i++) {
        int idx = tid + i * 256;
        int r   = idx / 48;
        int cc  = idx - r * 48;
        cp16(smb + W_OFF + r * (BP*4) + cc * 16, (const char*)(g_wp16 + (size_t)r * 192) + cc * 16);
    }
    CP_COMMIT();

#pragma unroll 1
    for (int k = 0; k < 32; k++) {
        const int buf = k & 1;
        if (k < 31) {
            const int k0n = (k + 1) * 32;
#pragma unroll
            for (int l = 0; l < 4; l++)
                xr[l] = *(const float4*)&x[(size_t)(row0 + xrr[l]) * EDIM + k0n + xcc[l]];
            const int kp0 = k0n >> 1;
            const uint32_t wdst = smb + W_OFF + ((k + 1) & 1) * 12800;
#pragma unroll
            for (int i = 0; i < 3; i++) {
                int idx = tid + i * 256;
                int r   = idx / 48;
                int cc  = idx - r * 48;
                cp16(wdst + r * (BP*4) + cc * 16, (const char*)(g_wp16 + (size_t)(kp0 + r) * 192) + cc * 16);
            }
            CP_COMMIT();
            asm volatile("cp.async.wait_group 1;" ::: "memory");
        } else {
            asm volatile("cp.async.wait_group 0;" ::: "memory");
        }
        __syncthreads();

        const uint32_t* Ah32 = (const uint32_t*)(sm + XH_OFF + buf * 10240);
        const uint32_t* Al32 = (const uint32_t*)(sm + XL_OFF + buf * 10240);
        const uint32_t* Bw   = (const uint32_t*)(sm + W_OFF  + buf * 12800);
        const int ap32 = AP / 2;    // 20

#pragma unroll
        for (int k16 = 0; k16 < 2; k16++) {
            uint32_t ah[4][4], al[4][4];
#pragma unroll
            for (int mt = 0; mt < 4; mt++) {
                int rb = (warpM * 64 + mt * 16 + g) * ap32 + k16 * 8 + tg;
                ah[mt][0] = Ah32[rb];
                ah[mt][1] = Ah32[rb + 8 * ap32];
                ah[mt][2] = Ah32[rb + 4];
                ah[mt][3] = Ah32[rb + 8 * ap32 + 4];
                al[mt][0] = Al32[rb];
                al[mt][1] = Al32[rb + 8 * ap32];
                al[mt][2] = Al32[rb + 4];
                al[mt][3] = Al32[rb + 8 * ap32 + 4];
            }
#pragma unroll
            for (int nt = 0; nt < 6; nt++) {
                int n  = warpN * 48 + nt * 8 + g;
                int kp = k16 * 8 + tg;
                uint32_t b0 = Bw[kp * BP + n], b1 = Bw[(kp + 4) * BP + n];
#pragma unroll
                for (int mt = 0; mt < 4; mt++) {
                    float* c = acc[mt][nt];
                    mma_f16(c[0], c[1], c[2], c[3], ah[mt][0], ah[mt][1], ah[mt][2], ah[mt][3], b0, b1);
                    mma_f16(c[0], c[1], c[2], c[3], al[mt][0], al[mt][1], al[mt][2], al[mt][3], b0, b1);
                }
            }
        }

        if (k < 31) {
            uint32_t* XH = (uint32_t*)(sm + XH_OFF + ((k + 1) & 1) * 10240);
            uint32_t* XL = (uint32_t*)(sm + XL_OFF + ((k + 1) & 1) * 10240);
#pragma unroll
            for (int l = 0; l < 4; l++) {
                uint32_t h0, l0, h1, l1;
                split_pack16(xr[l].x, xr[l].y, h0, l0);
                split_pack16(xr[l].z, xr[l].w, h1, l1);
                int base = (xrr[l] * AP + xcc[l]) >> 1;
                XH[base]     = h0;
                XH[base + 1] = h1;
                XL[base]     = l0;
                XL[base + 1] = l1;
            }
        }
        __syncthreads();
    }

    // ---- epilogue: K fp16 single, Q fp16 scaled hi/lo, V fp16 hi/lo pairs ----
    const float CQ = 0.125f * 1.44269504088896340736f;   // 1/sqrt(H) * log2(e)
#pragma unroll
    for (int mt = 0; mt < 4; mt++) {
#pragma unroll
        for (int nt = 0; nt < 6; nt++) {
            int gcol = warpN * 48 + nt * 8 + 2 * tg;
            int seg  = gcol >> 6;
            int cc   = gcol & 63;
            int r0   = row0 + warpM * 64 + mt * 16 + g;
            float* c = acc[mt][nt];
            if (seg == 2) {
                // V: pair adjacent seq rows (g even <-> g odd) via shfl, fp16 hi/lo
                float p0 = __shfl_xor_sync(0xffffffffu, c[0], 4);
                float p1 = __shfl_xor_sync(0xffffffffu, c[1], 4);
                float p2 = __shfl_xor_sync(0xffffffffu, c[2], 4);
                float p3 = __shfl_xor_sync(0xffffffffu, c[3], 4);
                if ((g & 1) == 0) {
                    uint32_t h0, l0, h1, l1;
                    split_pack16(c[0], p0, h0, l0);
                    split_pack16(c[1], p1, h1, l1);
                    int kp = r0 >> 1;
                    *(uint2*)&g_vph[kp * 64 + cc] = make_uint2(h0, h1);
                    *(uint2*)&g_vpl[kp * 64 + cc] = make_uint2(l0, l1);
                    split_pack16(c[2], p2, h0, l0);
                    split_pack16(c[3], p3, h1, l1);
                    int kp2 = (r0 + 8) >> 1;
                    *(uint2*)&g_vph[kp2 * 64 + cc] = make_uint2(h0, h1);
                    *(uint2*)&g_vpl[kp2 * 64 + cc] = make_uint2(l0, l1);
                }
            } else if (seg == 0) {
                // K: single fp16
                g_k16[r0 * 32 + cc / 2]       = pack_h16(c[0], c[1]);
                g_k16[(r0 + 8) * 32 + cc / 2] = pack_h16(c[2], c[3]);
            } else {
                // Q: scaled, fp16 hi/lo
                uint32_t hp, lp;
                split_pack16(c[0] * CQ, c[1] * CQ, hp, lp);
                g_qh[r0 * 32 + cc / 2] = hp;
                g_ql[r0 * 32 + cc / 2] = lp;
                split_pack16(c[2] * CQ, c[3] * CQ, hp, lp);
                g_qh[(r0 + 8) * 32 + cc / 2] = hp;
                g_ql[(r0 + 8) * 32 + cc / 2] = lp;
            }
        }
    }
}

// ---------------------------------------------------------------------------
// Kernel 2: causal flash attention, block-level split-K partials, fp16.
// (Proven round-12 version, unchanged.)
// QK = (Qh + Ql) * K; PV = P * (Vh + Vl). Stage 26624 B -> 4 blocks/SM.
// ---------------------------------------------------------------------------
#define KP32   36
#define VPP    68
#define STG    26624
#define VH_O   9216
#define VL_O   17920
#define ATTN_SMEM (2*STG)               // 53248; 4 blocks/SM = 212992

__device__ __forceinline__ void fill_kv(uint32_t sb, int t, int kt,
                                        const uint32_t* k16,
                                        const uint32_t* vph, const uint32_t* vpl)
{
    const int k0  = kt * 64;
    const int kp0 = k0 >> 1;
#pragma unroll
    for (int i = 0; i < 4; i++) {
        int idx = t + i * 128;
        int r   = idx >> 3;
        int cc  = (idx & 7) * 16;
        cp16(sb + r * 144 + cc, (const char*)(k16 + (size_t)(k0 + r) * 32) + cc);
    }
#pragma unroll
    for (int i = 0; i < 4; i++) {
        int idx = t + i * 128;
        int r   = idx >> 4;
        int cc  = (idx & 15) * 16;
        cp16(sb + VH_O + r * 272 + cc, (const char*)(vph + (size_t)(kp0 + r) * HDIM) + cc);
        cp16(sb + VL_O + r * 272 + cc, (const char*)(vpl + (size_t)(kp0 + r) * HDIM) + cc);
    }
}

__global__ void __launch_bounds__(128, 4) attn_kernel()
{
    extern __shared__ unsigned char smraw[];
    const uint32_t sb = smem_u32(smraw);

    const int tid  = threadIdx.x;
    const int lane = tid & 31;
    const int w    = tid >> 5;
    const int g    = lane >> 2;
    const int tg   = lane & 3;
    const int bx   = blockIdx.x;       // 512 blocks, heavy q-tiles first
    const int b    = bx & 7;
    const int half = (bx >> 3) & 1;
    const int qt   = 31 - (bx >> 4);
    const int q0   = qt * 64;
    const int n    = qt + 1;
    const int kb   = half ? (n >> 1) : 0;
    const int ke   = half ? n : (n >> 1);

    const uint32_t* K16g = g_k16 + (size_t)b * SEQ * 32;
    const uint32_t* Vphg = g_vph + (size_t)b * (SEQ/2) * HDIM;
    const uint32_t* Vplg = g_vpl + (size_t)b * (SEQ/2) * HDIM;
    const uint32_t* qh32 = g_qh + (size_t)b * SEQ * 32;
    const uint32_t* ql32 = g_ql + (size_t)b * SEQ * 32;

    const int rowq = w * 16 + g;
    const int gr0  = q0 + rowq;
    const int gr1  = gr0 + 8;
    uint32_t qfh[4][4], qfl[4][4];
    {
        int base = (q0 + rowq) * 32;
#pragma unroll
        for (int kk = 0; kk < 4; kk++) {
            int o0 = base + kk * 8 + tg;
            qfh[kk][0] = qh32[o0];
            qfh[kk][1] = qh32[o0 + 8 * 32];
            qfh[kk][2] = qh32[o0 + 4];
            qfh[kk][3] = qh32[o0 + 8 * 32 + 4];
            qfl[kk][0] = ql32[o0];
            qfl[kk][1] = ql32[o0 + 8 * 32];
            qfl[kk][2] = ql32[o0 + 4];
            qfl[kk][3] = ql32[o0 + 8 * 32 + 4];
        }
    }

    float m0 = -1e30f, m1 = -1e30f, l0s = 0.f, l1s = 0.f;
    float o[8][4];
#pragma unroll
    for (int nt = 0; nt < 8; nt++)
#pragma unroll
        for (int r = 0; r < 4; r++) o[nt][r] = 0.f;

    if (kb < ke) {
        fill_kv(sb + (kb & 1) * STG, tid, kb, K16g, Vphg, Vplg);
        CP_COMMIT();

#pragma unroll 1
        for (int kt = kb; kt < ke; kt++) {
            const int k0 = kt * 64;

            if (kt + 1 < ke) {
                fill_kv(sb + ((kt + 1) & 1) * STG, tid, kt + 1, K16g, Vphg, Vplg);
                CP_COMMIT();
                asm volatile("cp.async.wait_group 1;" ::: "memory");
            } else {
                asm volatile("cp.async.wait_group 0;" ::: "memory");
            }
            __syncthreads();

            const unsigned char* st = smraw + (kt & 1) * STG;
            const uint32_t* KH32 = (const uint32_t*)(st);
            const uint32_t* VPH  = (const uint32_t*)(st + VH_O);
            const uint32_t* VPL  = (const uint32_t*)(st + VL_O);

            // ---- S = Q K^T (Qh*K + Ql*K) ----
            float s[8][4];
#pragma unroll
            for (int nt = 0; nt < 8; nt++)
#pragma unroll
                for (int r = 0; r < 4; r++) s[nt][r] = 0.f;

#pragma unroll
            for (int kk = 0; kk < 4; kk++) {
#pragma unroll
                for (int nt = 0; nt < 8; nt++) {
                    int base = (nt * 8 + g) * KP32 + kk * 8 + tg;
                    uint32_t bh0 = KH32[base], bh1 = KH32[base + 4];
                    float* c = s[nt];
                    mma_f16(c[0], c[1], c[2], c[3], qfh[kk][0], qfh[kk][1], qfh[kk][2], qfh[kk][3], bh0, bh1);
                    mma_f16(c[0], c[1], c[2], c[3], qfl[kk][0], qfl[kk][1], qfl[kk][2], qfl[kk][3], bh0, bh1);
                }
            }

            // ---- causal mask (diagonal tile only) ----
            if (kt == qt) {
#pragma unroll
                for (int nt = 0; nt < 8; nt++) {
                    int c0 = k0 + nt * 8 + 2 * tg;
                    if (c0     > gr0) s[nt][0] = -1e30f;
                    if (c0 + 1 > gr0) s[nt][1] = -1e30f;
                    if (c0     > gr1) s[nt][2] = -1e30f;
                    if (c0 + 1 > gr1) s[nt][3] = -1e30f;
                }
            }

            // ---- online softmax ----
            float mA = -1e30f, mB = -1e30f;
#pragma unroll
            for (int nt = 0; nt < 8; nt++) {
                mA = fmaxf(mA, fmaxf(s[nt][0], s[nt][1]));
                mB = fmaxf(mB, fmaxf(s[nt][2], s[nt][3]));
            }
            mA = fmaxf(mA, __shfl_xor_sync(0xffffffffu, mA, 1));
            mA = fmaxf(mA, __shfl_xor_sync(0xffffffffu, mA, 2));
            mB = fmaxf(mB, __shfl_xor_sync(0xffffffffu, mB, 1));
            mB = fmaxf(mB, __shfl_xor_sync(0xffffffffu, mB, 2));
            float mn0 = fmaxf(m0, mA);
            float mn1 = fmaxf(m1, mB);
            float al0 = ex2f(m0 - mn0);
            float al1 = ex2f(m1 - mn1);
            m0 = mn0; m1 = mn1;

            float rs0 = 0.f, rs1 = 0.f;
#pragma unroll
            for (int nt = 0; nt < 8; nt++) {
                float p0 = ex2f(s[nt][0] - mn0);
                float p1 = ex2f(s[nt][1] - mn0);
                float p2 = ex2f(s[nt][2] - mn1);
                float p3 = ex2f(s[nt][3] - mn1);
                rs0 += p0 + p1;
                rs1 += p2 + p3;
                s[nt][0] = p0; s[nt][1] = p1; s[nt][2] = p2; s[nt][3] = p3;
            }
            rs0 += __shfl_xor_sync(0xffffffffu, rs0, 1);
            rs0 += __shfl_xor_sync(0xffffffffu, rs0, 2);
            rs1 += __shfl_xor_sync(0xffffffffu, rs1, 1);
            rs1 += __shfl_xor_sync(0xffffffffu, rs1, 2);
            l0s = l0s * al0 + rs0;
            l1s = l1s * al1 + rs1;

#pragma unroll
            for (int nt = 0; nt < 8; nt++) {
                o[nt][0] *= al0; o[nt][1] *= al0;
                o[nt][2] *= al1; o[nt][3] *= al1;
            }

            // ---- O += P V (P fp16 single; V hi + lo) ----
#pragma unroll
            for (int kk = 0; kk < 4; kk++) {
                uint32_t ah0 = pack_h16(s[2*kk  ][0], s[2*kk  ][1]);
                uint32_t ah1 = pack_h16(s[2*kk  ][2], s[2*kk  ][3]);
                uint32_t ah2 = pack_h16(s[2*kk+1][0], s[2*kk+1][1]);
                uint32_t ah3 = pack_h16(s[2*kk+1][2], s[2*kk+1][3]);
#pragma unroll
                for (int nt = 0; nt < 8; nt++) {
                    int h = nt * 8 + g;
                    uint32_t vb0h = VPH[(kk * 8 + tg) * VPP + h];
                    uint32_t vb1h = VPH[(kk * 8 + 4 + tg) * VPP + h];
                    uint32_t vb0l = VPL[(kk * 8 + tg) * VPP + h];
                    uint32_t vb1l = VPL[(kk * 8 + 4 + tg) * VPP + h];
                    float* c = o[nt];
                    mma_f16(c[0], c[1], c[2], c[3], ah0, ah1, ah2, ah3, vb0h, vb1h);
                    mma_f16(c[0], c[1], c[2], c[3], ah0, ah1, ah2, ah3, vb0l, vb1l);
                }
            }
            __syncthreads();   // release stage[kt&1] before next iter's prefetch
        }
    }

    // ---- epilogue: store unnormalized partials ----
    float* po = g_po[half];
    size_t ro0 = ((size_t)b * SEQ + gr0) * HDIM;
    size_t ro1 = ((size_t)b * SEQ + gr1) * HDIM;
#pragma unroll
    for (int nt = 0; nt < 8; nt++) {
        int c = nt * 8 + 2 * tg;
        *(float2*)&po[ro0 + c] = make_float2(o[nt][0], o[nt][1]);
        *(float2*)&po[ro1 + c] = make_float2(o[nt][2], o[nt][3]);
    }
    if (tg == 0) {
        g_pm[half][b * SEQ + gr0] = m0;
        g_pm[half][b * SEQ + gr1] = m1;
        g_pl[half][b * SEQ + gr0] = l0s;
        g_pl[half][b * SEQ + gr1] = l1s;
    }
}

// ---------------------------------------------------------------------------
// Kernel 3: merge split-K partials (proven version, unchanged).
// ---------------------------------------------------------------------------
__global__ void __launch_bounds__(256) merge_kernel(float* __restrict__ out)
{
    int idx  = blockIdx.x * 256 + threadIdx.x;
    int row  = idx >> 2;
    int base = idx * 4;

    float ma = g_pm[0][row], mb = g_pm[1][row];
    float la = g_pl[0][row], lb = g_pl[1][row];

    float4 a[4], c[4];
#pragma unroll
    for (int i = 0; i < 4; i++) a[i] = ((const float4*)g_po[0])[base + i];
#pragma unroll
    for (int i = 0; i < 4; i++) c[i] = ((const float4*)g_po[1])[base + i];

    float ms  = fmaxf(ma, mb);
    float sa  = ex2f(ma - ms);
    float sc  = ex2f(mb - ms);
    float inv = 1.f / (la * sa + lb * sc);
    sa *= inv;
    sc *= inv;

#pragma unroll
    for (int i = 0; i < 4; i++) {
        float4 r;
        r.x = a[i].x * sa + c[i].x * sc;
        r.y = a[i].y * sa + c[i].y * sc;
        r.z = a[i].z * sa + c[i].z * sc;
        r.w = a[i].w * sa + c[i].w * sc;
        ((float4*)out)[base + i] = r;
    }
}

// ---------------------------------------------------------------------------
extern "C" void kernel_launch(void* const* d_in, const int* in_sizes, int n_in,
                              void* d_out, int out_size)
{
    const float* x  = (const float*)d_in[0];
    const float* wk = (const float*)d_in[1];
    const float* wq = (const float*)d_in[2];
    const float* wv = (const float*)d_in[3];
    float* out = (float*)d_out;

    prep_w<<<384, 256>>>(wk, wq, wv);

    cudaFuncSetAttribute(proj_kernel,
                         cudaFuncAttributeMaxDynamicSharedMemorySize, PROJ_SMEM);
    proj_kernel<<<MTOT / 128, 256, PROJ_SMEM>>>(x);

    cudaFuncSetAttribute(attn_kernel,
                         cudaFuncAttributeMaxDynamicSharedMemorySize, ATTN_SMEM);
    attn_kernel<<<512, 128, ATTN_SMEM>>>();

    merge_kernel<<<256, 256>>>(out);
}